// round 13
// baseline (speedup 1.0000x reference)
#include <cuda_runtime.h>
#include <cstdint>

#define Bb   2
#define Ll   2048
#define Ssz  2048
#define Hh   16
#define Ee   64
#define BN   64
#define NTIL (Ssz / BN)          // 32
#define C0   0.18033688011112042f    // 0.125 * log2(e)
#define MPEN 1.8033688011112042e8f   // 1e9 * C0 (finite mask penalty, matches reference)

// one stage: K fp16 [64 s][144B] + V fp16 [64 s][176B] (d 0..63 data, d64=1.0, d65..79=0)
#define KH_OFF 0
#define VH_OFF 9216
#define VSTR   176
#define STAGE_BYTES 20480
#define NSTAGE 3
#define SM_BYTES (NSTAGE * STAGE_BYTES + 640)   // 62080; Q staging + epilogue reuse

__device__ unsigned int g_maskbits[(size_t)Bb * Ll * (Ssz / 32)];
// fp16 K/V, head-major [b,h,s,e], packed 2 per uint32
__device__ uint32_t g_kh[(size_t)Bb * Hh * Ssz * Ee / 2];
__device__ uint32_t g_vh[(size_t)Bb * Hh * Ssz * Ee / 2];

__device__ __forceinline__ uint32_t smem_u32(const void* p) {
    uint32_t a;
    asm("{ .reg .u64 t; cvta.to.shared.u64 t, %1; cvt.u32.u64 %0, t; }" : "=r"(a) : "l"(p));
    return a;
}
__device__ __forceinline__ uint32_t packf16(float lo, float hi) {   // low 16 bits <- lo
    uint32_t r; asm("cvt.rn.f16x2.f32 %0, %1, %2;" : "=r"(r) : "f"(hi), "f"(lo)); return r;
}
__device__ __forceinline__ void unpkf16(uint32_t w, float& a, float& b) {
    asm("{ .reg .b16 l,h; mov.b32 {l,h}, %2; cvt.f32.f16 %0, l; cvt.f32.f16 %1, h; }"
        : "=f"(a), "=f"(b) : "r"(w));
}
__device__ __forceinline__ void bsplit16(float f0, float f1, uint32_t& hw, uint32_t& lw) {
    hw = packf16(f0, f1);
    float h0, h1;
    unpkf16(hw, h0, h1);
    lw = packf16(f0 - h0, f1 - h1);
}
__device__ __forceinline__ void ex2h2(uint32_t& x) {
    asm("ex2.approx.f16x2 %0, %0;" : "+r"(x));
}
__device__ __forceinline__ void ldm4(uint32_t& r0, uint32_t& r1, uint32_t& r2, uint32_t& r3,
                                     uint32_t a) {
    asm volatile("ldmatrix.sync.aligned.m8n8.x4.shared.b16 {%0,%1,%2,%3}, [%4];"
                 : "=r"(r0), "=r"(r1), "=r"(r2), "=r"(r3) : "r"(a));
}
__device__ __forceinline__ void ldm4t(uint32_t& r0, uint32_t& r1, uint32_t& r2, uint32_t& r3,
                                      uint32_t a) {
    asm volatile("ldmatrix.sync.aligned.m8n8.x4.trans.shared.b16 {%0,%1,%2,%3}, [%4];"
                 : "=r"(r0), "=r"(r1), "=r"(r2), "=r"(r3) : "r"(a));
}
__device__ __forceinline__ void ldm2t(uint32_t& r0, uint32_t& r1, uint32_t a) {
    asm volatile("ldmatrix.sync.aligned.m8n8.x2.trans.shared.b16 {%0,%1}, [%2];"
                 : "=r"(r0), "=r"(r1) : "r"(a));
}
__device__ __forceinline__ void mma16816(float* c, const uint32_t* a, uint32_t b0, uint32_t b1) {
    asm volatile("mma.sync.aligned.m16n8k16.row.col.f32.f16.f16.f32 "
                 "{%0,%1,%2,%3},{%4,%5,%6,%7},{%8,%9},{%0,%1,%2,%3};"
                 : "+f"(c[0]), "+f"(c[1]), "+f"(c[2]), "+f"(c[3])
                 : "r"(a[0]), "r"(a[1]), "r"(a[2]), "r"(a[3]), "r"(b0), "r"(b1));
}
__device__ __forceinline__ void g_load8(const float* p, float* r) {
    float4 a = ((const float4*)p)[0];
    float4 b = ((const float4*)p)[1];
    r[0] = a.x; r[1] = a.y; r[2] = a.z; r[3] = a.w;
    r[4] = b.x; r[5] = b.y; r[6] = b.z; r[7] = b.w;
}
#define CP16(dst, src) asm volatile("cp.async.cg.shared.global [%0], [%1], 16;" \
                                    :: "r"(dst), "l"(src) : "memory")
#define CP_COMMIT() asm volatile("cp.async.commit_group;" ::: "memory")
#define CP_WAIT1()  asm volatile("cp.async.wait_group 1;" ::: "memory")

// ---- fused pre-pass: blocks [0,2048) -> maskbits, [2048,4096) -> K/V fp16 convert ----
__global__ void prep_kernel(const float* __restrict__ msk,
                            const float* __restrict__ K, const float* __restrict__ V) {
    if (blockIdx.x < 2048) {
        const int T = blockIdx.x * 256 + threadIdx.x;
        const float4* p = (const float4*)(msk + (size_t)T * 16);
        float4 v0 = p[0], v1 = p[1], v2 = p[2], v3 = p[3];
        uint32_t bits = 0;
        bits |= (v0.x > 0.5f) ? 1u : 0u;        bits |= (v0.y > 0.5f) ? 2u : 0u;
        bits |= (v0.z > 0.5f) ? 4u : 0u;        bits |= (v0.w > 0.5f) ? 8u : 0u;
        bits |= (v1.x > 0.5f) ? 16u : 0u;       bits |= (v1.y > 0.5f) ? 32u : 0u;
        bits |= (v1.z > 0.5f) ? 64u : 0u;       bits |= (v1.w > 0.5f) ? 128u : 0u;
        bits |= (v2.x > 0.5f) ? 256u : 0u;      bits |= (v2.y > 0.5f) ? 512u : 0u;
        bits |= (v2.z > 0.5f) ? 1024u : 0u;     bits |= (v2.w > 0.5f) ? 2048u : 0u;
        bits |= (v3.x > 0.5f) ? 4096u : 0u;     bits |= (v3.y > 0.5f) ? 8192u : 0u;
        bits |= (v3.z > 0.5f) ? 16384u : 0u;    bits |= (v3.w > 0.5f) ? 32768u : 0u;
        uint32_t x = bits << (16 * (T & 1));
        x |= __shfl_xor_sync(0xffffffffu, x, 1);
        if (!(T & 1)) g_maskbits[T >> 1] = x;
    } else {
        size_t idx = (size_t)(blockIdx.x - 2048) * 256 + threadIdx.x;
        int c = (int)(idx & 7);
        int s = (int)((idx >> 3) & (Ssz - 1));
        int h = (int)((idx >> 14) & (Hh - 1));
        int b = (int)(idx >> 18);
        size_t src = (((size_t)b * Ssz + s) * Hh + h) * Ee + c * 8;
        size_t dst4 = ((((size_t)b * Hh + h) * Ssz + s) * Ee + c * 8) >> 1;
        float kr[8], vr[8];
        g_load8(K + src, kr);
        g_load8(V + src, vr);
        uint4 ko = make_uint4(packf16(kr[0], kr[1]), packf16(kr[2], kr[3]),
                              packf16(kr[4], kr[5]), packf16(kr[6], kr[7]));
        uint4 vo = make_uint4(packf16(vr[0], vr[1]), packf16(vr[2], vr[3]),
                              packf16(vr[4], vr[5]), packf16(vr[6], vr[7]));
        *(uint4*)&g_kh[dst4] = ko;
        *(uint4*)&g_vh[dst4] = vo;
    }
}

__global__ __launch_bounds__(512, 1)
void fa_mma_kernel(const float* __restrict__ Q, float* __restrict__ O)
{
    extern __shared__ char smbuf[];
    const uint32_t sb = smem_u32(smbuf);

    const int tid  = threadIdx.x;
    const int wid  = tid >> 5;
    const int lane = tid & 31;
    const int wg   = wid >> 3;          // n-half: 0 -> keys [0,32), 1 -> [32,64)
    const int wm   = wid & 7;           // row group: rows wm*16 .. wm*16+15
    const int g    = lane >> 2;
    const int tg   = lane & 3;
    const int mtile = blockIdx.x, h = blockIdx.y, b = blockIdx.z;
    const int rloc0 = wm * 16 + g;
    const int r0g   = mtile * 128 + rloc0;

    const int bar_id = 1 + wg;
    #define GBAR() asm volatile("bar.sync %0, 256;" :: "r"(bar_id) : "memory")

    // ---- stage Q (scaled by C0) as fp16 hi/lo into smem ----
    {
        const int row = tid >> 2, dh = tid & 3;
        const float* qg = Q + ((size_t)(b * Ll + mtile * 128 + row) * Hh + h) * Ee + dh * 16;
        float qv[16];
        g_load8(qg, qv);
        g_load8(qg + 8, qv + 8);
        uint32_t hw[8], lw[8];
        #pragma unroll
        for (int i = 0; i < 8; i++) bsplit16(qv[2*i] * C0, qv[2*i+1] * C0, hw[i], lw[i]);
        char* qh_dst = smbuf + row * 144 + dh * 32;
        char* ql_dst = qh_dst + 18432;
        ((uint4*)qh_dst)[0] = make_uint4(hw[0], hw[1], hw[2], hw[3]);
        ((uint4*)qh_dst)[1] = make_uint4(hw[4], hw[5], hw[6], hw[7]);
        ((uint4*)ql_dst)[0] = make_uint4(lw[0], lw[1], lw[2], lw[3]);
        ((uint4*)ql_dst)[1] = make_uint4(lw[4], lw[5], lw[6], lw[7]);
    }
    __syncthreads();

    uint32_t qh[4][4], ql[4][4];
    {
        uint32_t qoff = (uint32_t)((wm * 16 + ((lane >> 3) & 1) * 8 + (lane & 7)) * 144
                                   + (lane >> 4) * 16);
        #pragma unroll
        for (int kk = 0; kk < 4; kk++) {
            ldm4(qh[kk][0], qh[kk][1], qh[kk][2], qh[kk][3], sb + qoff + kk * 32);
            ldm4(ql[kk][0], ql[kk][1], ql[kk][2], ql[kk][3], sb + 18432 + qoff + kk * 32);
        }
    }
    __syncthreads();   // Q consumed (both groups); smem free for K/V stages

    // fragment offsets
    const uint32_t kfoff = (uint32_t)((((lane >> 4) * 8 + (lane & 7)) * 144)
                                      + ((lane >> 3) & 1) * 16 + wg * 4608);
    const uint32_t vfoff = (uint32_t)((((lane & 7) + ((lane >> 3) & 1) * 8) * VSTR)
                                      + (lane >> 4) * 16 + wg * (32 * VSTR));

    // cp.async fill mapping: thread -> row r=tid>>3 (0..63), 16B chunk c=tid&7.
    const int frow = tid >> 3, fc = tid & 7;
    const char* KhB = (const char*)g_kh + ((((size_t)b * Hh + h) * Ssz + frow) * Ee + fc * 8) * 2;
    const char* VhB = (const char*)g_vh + ((((size_t)b * Hh + h) * Ssz + frow) * Ee + fc * 8) * 2;
    const uint32_t fdstK = (uint32_t)(frow * 144 + fc * 16);
    const uint32_t fdstV = (uint32_t)(frow * VSTR + fc * 16);

    // ---- V pad columns d64..79: d64 = fp16 1.0 (l-sum ones column), rest 0 ----
    {
        const int pr = tid >> 3, pw = tid & 7;
        uint32_t val = (pw == 0) ? 0x00003C00u : 0u;
        #pragma unroll
        for (int st = 0; st < NSTAGE; st++)
            *(uint32_t*)(smbuf + st * STAGE_BYTES + VH_OFF + pr * VSTR + 128 + pw * 4) = val;
    }

    // ---- prologue: fill stages 0,1 with tiles 0,1 ----
    CP16(sb + KH_OFF + fdstK, KhB);
    CP16(sb + VH_OFF + fdstV, VhB);
    CP_COMMIT();
    {
        size_t goff = (size_t)BN * Ee * 2;
        CP16(sb + STAGE_BYTES + KH_OFF + fdstK, KhB + goff);
        CP16(sb + STAGE_BYTES + VH_OFF + fdstV, VhB + goff);
    }
    CP_COMMIT();
    CP_WAIT1();    // tile 0 landed
    GBAR();

    float Oa[8][4];
    #pragma unroll
    for (int nd = 0; nd < 8; nd++)
        #pragma unroll
        for (int j = 0; j < 4; j++) Oa[nd][j] = 0.0f;
    float Ol[4] = {0.0f, 0.0f, 0.0f, 0.0f};   // l-sum accumulator (ones-column tile)

    const size_t mrow0 = ((size_t)(b * Ll + r0g)) * (Ssz / 32);
    const size_t mrow1 = mrow0 + 8 * (Ssz / 32);

    uint32_t comp_off = 0;
    uint32_t fill_off = 2 * STAGE_BYTES;

    for (int t = 0; t < NTIL; t++) {
        if (t + 2 < NTIL) {
            const uint32_t stn = sb + fill_off;
            size_t goff = (size_t)(t + 2) * BN * Ee * 2;
            CP16(stn + KH_OFF + fdstK, KhB + goff);
            CP16(stn + VH_OFF + fdstV, VhB + goff);
        }
        CP_COMMIT();

        const uint32_t stb = sb + comp_off;

        // ---- S = (q_hi + q_lo) * K  (A-side fp16 split; K read once) ----
        float c_[4][4];
        #pragma unroll
        for (int nt = 0; nt < 4; nt++)
            #pragma unroll
            for (int j = 0; j < 4; j++) c_[nt][j] = 0.0f;

        #pragma unroll
        for (int kk = 0; kk < 4; kk++) {
            #pragma unroll
            for (int p = 0; p < 2; p++) {
                uint32_t a = stb + KH_OFF + (uint32_t)(p * 2304) + (uint32_t)(kk * 32) + kfoff;
                uint32_t k0, k1, k2, k3;
                ldm4(k0, k1, k2, k3, a);
                mma16816(c_[2*p],     qh[kk], k0, k1);
                mma16816(c_[2*p + 1], qh[kk], k2, k3);
                mma16816(c_[2*p],     ql[kk], k0, k1);
                mma16816(c_[2*p + 1], ql[kk], k2, k3);
            }
        }

        // ---- mask (one word per row per tile-half; all-ones fast path) ----
        {
            uint32_t w0 = g_maskbits[mrow0 + t * 2 + wg];
            uint32_t w1 = g_maskbits[mrow1 + t * 2 + wg];
            if ((w0 & w1) != 0xFFFFFFFFu) {
                #pragma unroll
                for (int nt = 0; nt < 4; nt++) {
                    int bit = nt * 8 + 2 * tg;
                    if (!((w0 >> bit) & 1u))       c_[nt][0] -= MPEN;
                    if (!((w0 >> (bit + 1)) & 1u)) c_[nt][1] -= MPEN;
                    if (!((w1 >> bit) & 1u))       c_[nt][2] -= MPEN;
                    if (!((w1 >> (bit + 1)) & 1u)) c_[nt][3] -= MPEN;
                }
            }
        }

        // ---- softmax: p = 2^z directly in fp16x2 (2^-ZOFF scale cancels in normalize) ----
        uint32_t ph[2][4];
        #pragma unroll
        for (int kk = 0; kk < 2; kk++) {
            ph[kk][0] = packf16(c_[2*kk][0],     c_[2*kk][1]);
            ph[kk][1] = packf16(c_[2*kk][2],     c_[2*kk][3]);
            ph[kk][2] = packf16(c_[2*kk + 1][0], c_[2*kk + 1][1]);
            ph[kk][3] = packf16(c_[2*kk + 1][2], c_[2*kk + 1][3]);
            ex2h2(ph[kk][0]); ex2h2(ph[kk][1]); ex2h2(ph[kk][2]); ex2h2(ph[kk][3]);
        }

        // ---- O += P * V ; l via ones-column (d64) tensor-summed into Ol ----
        #pragma unroll
        for (int kk = 0; kk < 2; kk++) {
            #pragma unroll
            for (int p = 0; p < 4; p++) {
                uint32_t a = stb + VH_OFF + (uint32_t)(kk * (16 * VSTR))
                           + (uint32_t)(p * 32) + vfoff;
                uint32_t v0, v1, v2, v3;
                ldm4t(v0, v1, v2, v3, a);
                mma16816(Oa[2*p],     ph[kk], v0, v1);
                mma16816(Oa[2*p + 1], ph[kk], v2, v3);
            }
            {
                uint32_t a = stb + VH_OFF + (uint32_t)(kk * (16 * VSTR))
                           + (uint32_t)(4 * 32) + vfoff;
                uint32_t v0, v1;
                ldm2t(v0, v1, a);
                mma16816(Ol, ph[kk], v0, v1);
            }
        }

        CP_WAIT1();
        GBAR();

        comp_off += STAGE_BYTES; if (comp_off == NSTAGE * STAGE_BYTES) comp_off = 0;
        fill_off += STAGE_BYTES; if (fill_off == NSTAGE * STAGE_BYTES) fill_off = 0;
    }

    // ---- l lives in the d64 column (tg==0 lanes); broadcast within each quad ----
    float l0 = __shfl_sync(0xffffffffu, Ol[0], lane & ~3);
    float l1 = __shfl_sync(0xffffffffu, Ol[2], lane & ~3);

    __syncthreads();   // join groups; both done reading stages before smem reuse

    float* sOut = (float*)smbuf;                                // [128][72] fp32
    float* sL   = (float*)(smbuf + NSTAGE * STAGE_BYTES);       // [128] fp32
    const int rloc1 = rloc0 + 8;

    if (wg == 0) {
        #pragma unroll
        for (int nd = 0; nd < 8; nd++) {
            int col = nd * 8 + 2 * tg;
            *(float2*)&sOut[rloc0 * 72 + col] = make_float2(Oa[nd][0], Oa[nd][1]);
            *(float2*)&sOut[rloc1 * 72 + col] = make_float2(Oa[nd][2], Oa[nd][3]);
        }
        if (tg == 0) { sL[rloc0] = l0; sL[rloc1] = l1; }
    }
    __syncthreads();
    if (wg == 1) {
        float inv0 = 1.0f / (l0 + sL[rloc0]);
        float inv1 = 1.0f / (l1 + sL[rloc1]);
        float* o0 = O + ((size_t)((b * Hh + h) * Ll) + r0g) * Ee;
        float* o1 = o0 + (size_t)8 * Ee;
        #pragma unroll
        for (int nd = 0; nd < 8; nd++) {
            int col = nd * 8 + 2 * tg;
            float2 a0 = *(float2*)&sOut[rloc0 * 72 + col];
            float2 a1 = *(float2*)&sOut[rloc1 * 72 + col];
            *(float2*)(o0 + col) = make_float2((Oa[nd][0] + a0.x) * inv0,
                                               (Oa[nd][1] + a0.y) * inv0);
            *(float2*)(o1 + col) = make_float2((Oa[nd][2] + a1.x) * inv1,
                                               (Oa[nd][3] + a1.y) * inv1);
        }
    }
    #undef GBAR
}

extern "C" void kernel_launch(void* const* d_in, const int* in_sizes, int n_in,
                              void* d_out, int out_size)
{
    const float* Q = (const float*)d_in[0];
    const float* K = (const float*)d_in[1];
    const float* V = (const float*)d_in[2];
    const float* M = (const float*)d_in[3];
    float* O = (float*)d_out;

    prep_kernel<<<4096, 256>>>(M, K, V);

    cudaFuncSetAttribute(fa_mma_kernel, cudaFuncAttributeMaxDynamicSharedMemorySize, SM_BYTES);
    dim3 grid(Ll / 128, Hh, Bb);
    fa_mma_kernel<<<grid, 512, SM_BYTES>>>(Q, O);
}

// round 14
// speedup vs baseline: 1.0806x; 1.0806x over previous
#include <cuda_runtime.h>
#include <cstdint>

#define Bb   2
#define Ll   2048
#define Ssz  2048
#define Hh   16
#define Ee   64
#define BN   64
#define BM   64
#define NTIL (Ssz / BN)          // 32
#define C0   0.18033688011112042f    // 0.125 * log2(e)
#define MPEN 1.8033688011112042e8f   // 1e9 * C0 (finite mask penalty, matches reference)

// one stage: K fp16 [64 s][144B] + V fp16 [64 s][176B] (d 0..63 data, d64=1.0 ones col)
#define KH_OFF 0
#define VH_OFF 9216
#define VSTR   176
#define STAGE_BYTES 20480
#define NSTAGE 3
#define SM_BYTES (NSTAGE * STAGE_BYTES + 640)   // 62080 per CTA; x2 CTAs = 124160 <= 228KB

__device__ unsigned int g_maskbits[(size_t)Bb * Ll * (Ssz / 32)];
// fp16 K/V, head-major [b,h,s,e], packed 2 per uint32
__device__ uint32_t g_kh[(size_t)Bb * Hh * Ssz * Ee / 2];
__device__ uint32_t g_vh[(size_t)Bb * Hh * Ssz * Ee / 2];

__device__ __forceinline__ uint32_t smem_u32(const void* p) {
    uint32_t a;
    asm("{ .reg .u64 t; cvta.to.shared.u64 t, %1; cvt.u32.u64 %0, t; }" : "=r"(a) : "l"(p));
    return a;
}
__device__ __forceinline__ uint32_t packf16(float lo, float hi) {   // low 16 bits <- lo
    uint32_t r; asm("cvt.rn.f16x2.f32 %0, %1, %2;" : "=r"(r) : "f"(hi), "f"(lo)); return r;
}
__device__ __forceinline__ void unpkf16(uint32_t w, float& a, float& b) {
    asm("{ .reg .b16 l,h; mov.b32 {l,h}, %2; cvt.f32.f16 %0, l; cvt.f32.f16 %1, h; }"
        : "=f"(a), "=f"(b) : "r"(w));
}
__device__ __forceinline__ void bsplit16(float f0, float f1, uint32_t& hw, uint32_t& lw) {
    hw = packf16(f0, f1);
    float h0, h1;
    unpkf16(hw, h0, h1);
    lw = packf16(f0 - h0, f1 - h1);
}
__device__ __forceinline__ void ex2h2(uint32_t& x) {
    asm("ex2.approx.f16x2 %0, %0;" : "+r"(x));
}
__device__ __forceinline__ void ldm4(uint32_t& r0, uint32_t& r1, uint32_t& r2, uint32_t& r3,
                                     uint32_t a) {
    asm volatile("ldmatrix.sync.aligned.m8n8.x4.shared.b16 {%0,%1,%2,%3}, [%4];"
                 : "=r"(r0), "=r"(r1), "=r"(r2), "=r"(r3) : "r"(a));
}
__device__ __forceinline__ void ldm4t(uint32_t& r0, uint32_t& r1, uint32_t& r2, uint32_t& r3,
                                      uint32_t a) {
    asm volatile("ldmatrix.sync.aligned.m8n8.x4.trans.shared.b16 {%0,%1,%2,%3}, [%4];"
                 : "=r"(r0), "=r"(r1), "=r"(r2), "=r"(r3) : "r"(a));
}
__device__ __forceinline__ void ldm2t(uint32_t& r0, uint32_t& r1, uint32_t a) {
    asm volatile("ldmatrix.sync.aligned.m8n8.x2.trans.shared.b16 {%0,%1}, [%2];"
                 : "=r"(r0), "=r"(r1) : "r"(a));
}
__device__ __forceinline__ void mma16816(float* c, const uint32_t* a, uint32_t b0, uint32_t b1) {
    asm volatile("mma.sync.aligned.m16n8k16.row.col.f32.f16.f16.f32 "
                 "{%0,%1,%2,%3},{%4,%5,%6,%7},{%8,%9},{%0,%1,%2,%3};"
                 : "+f"(c[0]), "+f"(c[1]), "+f"(c[2]), "+f"(c[3])
                 : "r"(a[0]), "r"(a[1]), "r"(a[2]), "r"(a[3]), "r"(b0), "r"(b1));
}
__device__ __forceinline__ void g_load8(const float* p, float* r) {
    float4 a = ((const float4*)p)[0];
    float4 b = ((const float4*)p)[1];
    r[0] = a.x; r[1] = a.y; r[2] = a.z; r[3] = a.w;
    r[4] = b.x; r[5] = b.y; r[6] = b.z; r[7] = b.w;
}
#define CP16(dst, src) asm volatile("cp.async.cg.shared.global [%0], [%1], 16;" \
                                    :: "r"(dst), "l"(src) : "memory")
#define CP_COMMIT() asm volatile("cp.async.commit_group;" ::: "memory")
#define CP_WAIT1()  asm volatile("cp.async.wait_group 1;" ::: "memory")

// ---- fused pre-pass: blocks [0,2048) -> maskbits, [2048,4096) -> K/V fp16 convert ----
__global__ void prep_kernel(const float* __restrict__ msk,
                            const float* __restrict__ K, const float* __restrict__ V) {
    if (blockIdx.x < 2048) {
        const int T = blockIdx.x * 256 + threadIdx.x;
        const float4* p = (const float4*)(msk + (size_t)T * 16);
        float4 v0 = p[0], v1 = p[1], v2 = p[2], v3 = p[3];
        uint32_t bits = 0;
        bits |= (v0.x > 0.5f) ? 1u : 0u;        bits |= (v0.y > 0.5f) ? 2u : 0u;
        bits |= (v0.z > 0.5f) ? 4u : 0u;        bits |= (v0.w > 0.5f) ? 8u : 0u;
        bits |= (v1.x > 0.5f) ? 16u : 0u;       bits |= (v1.y > 0.5f) ? 32u : 0u;
        bits |= (v1.z > 0.5f) ? 64u : 0u;       bits |= (v1.w > 0.5f) ? 128u : 0u;
        bits |= (v2.x > 0.5f) ? 256u : 0u;      bits |= (v2.y > 0.5f) ? 512u : 0u;
        bits |= (v2.z > 0.5f) ? 1024u : 0u;     bits |= (v2.w > 0.5f) ? 2048u : 0u;
        bits |= (v3.x > 0.5f) ? 4096u : 0u;     bits |= (v3.y > 0.5f) ? 8192u : 0u;
        bits |= (v3.z > 0.5f) ? 16384u : 0u;    bits |= (v3.w > 0.5f) ? 32768u : 0u;
        uint32_t x = bits << (16 * (T & 1));
        x |= __shfl_xor_sync(0xffffffffu, x, 1);
        if (!(T & 1)) g_maskbits[T >> 1] = x;
    } else {
        size_t idx = (size_t)(blockIdx.x - 2048) * 256 + threadIdx.x;
        int c = (int)(idx & 7);
        int s = (int)((idx >> 3) & (Ssz - 1));
        int h = (int)((idx >> 14) & (Hh - 1));
        int b = (int)(idx >> 18);
        size_t src = (((size_t)b * Ssz + s) * Hh + h) * Ee + c * 8;
        size_t dst4 = ((((size_t)b * Hh + h) * Ssz + s) * Ee + c * 8) >> 1;
        float kr[8], vr[8];
        g_load8(K + src, kr);
        g_load8(V + src, vr);
        uint4 ko = make_uint4(packf16(kr[0], kr[1]), packf16(kr[2], kr[3]),
                              packf16(kr[4], kr[5]), packf16(kr[6], kr[7]));
        uint4 vo = make_uint4(packf16(vr[0], vr[1]), packf16(vr[2], vr[3]),
                              packf16(vr[4], vr[5]), packf16(vr[6], vr[7]));
        *(uint4*)&g_kh[dst4] = ko;
        *(uint4*)&g_vh[dst4] = vo;
    }
}

__global__ __launch_bounds__(256, 2)
void fa_mma_kernel(const float* __restrict__ Q, float* __restrict__ O)
{
    extern __shared__ char smbuf[];
    const uint32_t sb = smem_u32(smbuf);

    const int tid  = threadIdx.x;
    const int wid  = tid >> 5;
    const int lane = tid & 31;
    const int wg   = wid >> 2;          // n-half: 0 -> keys [0,32), 1 -> [32,64)
    const int wm   = wid & 3;           // row group: rows wm*16 .. wm*16+15
    const int g    = lane >> 2;
    const int tg   = lane & 3;
    const int mtile = blockIdx.x, h = blockIdx.y, b = blockIdx.z;
    const int rloc0 = wm * 16 + g;
    const int r0g   = mtile * BM + rloc0;

    const int bar_id = 1 + wg;
    #define GBAR() asm volatile("bar.sync %0, 128;" :: "r"(bar_id) : "memory")

    // ---- stage Q (scaled by C0) as fp16 hi/lo into smem (256 thr: 16 floats each) ----
    {
        const int row = tid >> 2, dh = tid & 3;
        const float* qg = Q + ((size_t)(b * Ll + mtile * BM + row) * Hh + h) * Ee + dh * 16;
        float qv[16];
        g_load8(qg, qv);
        g_load8(qg + 8, qv + 8);
        uint32_t hw[8], lw[8];
        #pragma unroll
        for (int i = 0; i < 8; i++) bsplit16(qv[2*i] * C0, qv[2*i+1] * C0, hw[i], lw[i]);
        char* qh_dst = smbuf + row * 144 + dh * 32;
        char* ql_dst = qh_dst + 9216;
        ((uint4*)qh_dst)[0] = make_uint4(hw[0], hw[1], hw[2], hw[3]);
        ((uint4*)qh_dst)[1] = make_uint4(hw[4], hw[5], hw[6], hw[7]);
        ((uint4*)ql_dst)[0] = make_uint4(lw[0], lw[1], lw[2], lw[3]);
        ((uint4*)ql_dst)[1] = make_uint4(lw[4], lw[5], lw[6], lw[7]);
    }
    __syncthreads();

    uint32_t qh[4][4], ql[4][4];
    {
        uint32_t qoff = (uint32_t)((wm * 16 + ((lane >> 3) & 1) * 8 + (lane & 7)) * 144
                                   + (lane >> 4) * 16);
        #pragma unroll
        for (int kk = 0; kk < 4; kk++) {
            ldm4(qh[kk][0], qh[kk][1], qh[kk][2], qh[kk][3], sb + qoff + kk * 32);
            ldm4(ql[kk][0], ql[kk][1], ql[kk][2], ql[kk][3], sb + 9216 + qoff + kk * 32);
        }
    }
    __syncthreads();   // Q consumed; smem free for K/V stages

    // fragment offsets
    const uint32_t kfoff = (uint32_t)((((lane >> 4) * 8 + (lane & 7)) * 144)
                                      + ((lane >> 3) & 1) * 16 + wg * 4608);
    const uint32_t vfoff = (uint32_t)((((lane & 7) + ((lane >> 3) & 1) * 8) * VSTR)
                                      + (lane >> 4) * 16 + wg * (32 * VSTR));

    // cp.async fill: thread -> row frow=tid>>2 (0..63), chunks fc2,fc2+1 (16B each).
    // tid<128 fills rows 0-31 (group 0's fragment region), tid>=128 rows 32-63.
    const int frow = tid >> 2, fc2 = (tid & 3) * 2;
    const char* KhB = (const char*)g_kh + ((((size_t)b * Hh + h) * Ssz + frow) * Ee + fc2 * 8) * 2;
    const char* VhB = (const char*)g_vh + ((((size_t)b * Hh + h) * Ssz + frow) * Ee + fc2 * 8) * 2;
    const uint32_t fdstK = (uint32_t)(frow * 144 + fc2 * 16);
    const uint32_t fdstV = (uint32_t)(frow * VSTR + fc2 * 16);

    // ---- V pad word at +128 per row: d64 = fp16 1.0 (ones column for l-sum) ----
    {
        const int pr = tid >> 2, pw = tid & 3;
        uint32_t val = (pw == 0) ? 0x00003C00u : 0u;
        #pragma unroll
        for (int st = 0; st < NSTAGE; st++)
            *(uint32_t*)(smbuf + st * STAGE_BYTES + VH_OFF + pr * VSTR + 128 + pw * 4) = val;
    }

    // ---- prologue: fill stages 0,1 with tiles 0,1 ----
    CP16(sb + KH_OFF + fdstK, KhB);
    CP16(sb + KH_OFF + fdstK + 16, KhB + 16);
    CP16(sb + VH_OFF + fdstV, VhB);
    CP16(sb + VH_OFF + fdstV + 16, VhB + 16);
    CP_COMMIT();
    {
        size_t goff = (size_t)BN * Ee * 2;
        CP16(sb + STAGE_BYTES + KH_OFF + fdstK, KhB + goff);
        CP16(sb + STAGE_BYTES + KH_OFF + fdstK + 16, KhB + goff + 16);
        CP16(sb + STAGE_BYTES + VH_OFF + fdstV, VhB + goff);
        CP16(sb + STAGE_BYTES + VH_OFF + fdstV + 16, VhB + goff + 16);
    }
    CP_COMMIT();
    CP_WAIT1();    // tile 0 landed
    GBAR();

    float Oa[8][4];
    #pragma unroll
    for (int nd = 0; nd < 8; nd++)
        #pragma unroll
        for (int j = 0; j < 4; j++) Oa[nd][j] = 0.0f;
    float Ol[4] = {0.0f, 0.0f, 0.0f, 0.0f};

    const size_t mrow0 = ((size_t)(b * Ll + r0g)) * (Ssz / 32);
    const size_t mrow1 = mrow0 + 8 * (Ssz / 32);

    uint32_t comp_off = 0;
    uint32_t fill_off = 2 * STAGE_BYTES;

    for (int t = 0; t < NTIL; t++) {
        if (t + 2 < NTIL) {
            const uint32_t stn = sb + fill_off;
            size_t goff = (size_t)(t + 2) * BN * Ee * 2;
            CP16(stn + KH_OFF + fdstK, KhB + goff);
            CP16(stn + KH_OFF + fdstK + 16, KhB + goff + 16);
            CP16(stn + VH_OFF + fdstV, VhB + goff);
            CP16(stn + VH_OFF + fdstV + 16, VhB + goff + 16);
        }
        CP_COMMIT();

        const uint32_t stb = sb + comp_off;

        // ---- S = (q_hi + q_lo) * K ----
        float c_[4][4];
        #pragma unroll
        for (int nt = 0; nt < 4; nt++)
            #pragma unroll
            for (int j = 0; j < 4; j++) c_[nt][j] = 0.0f;

        #pragma unroll
        for (int kk = 0; kk < 4; kk++) {
            #pragma unroll
            for (int p = 0; p < 2; p++) {
                uint32_t a = stb + KH_OFF + (uint32_t)(p * 2304) + (uint32_t)(kk * 32) + kfoff;
                uint32_t k0, k1, k2, k3;
                ldm4(k0, k1, k2, k3, a);
                mma16816(c_[2*p],     qh[kk], k0, k1);
                mma16816(c_[2*p + 1], qh[kk], k2, k3);
                mma16816(c_[2*p],     ql[kk], k0, k1);
                mma16816(c_[2*p + 1], ql[kk], k2, k3);
            }
        }

        // ---- mask (one word per row per tile-half; all-ones fast path) ----
        {
            uint32_t w0 = g_maskbits[mrow0 + t * 2 + wg];
            uint32_t w1 = g_maskbits[mrow1 + t * 2 + wg];
            if ((w0 & w1) != 0xFFFFFFFFu) {
                #pragma unroll
                for (int nt = 0; nt < 4; nt++) {
                    int bit = nt * 8 + 2 * tg;
                    if (!((w0 >> bit) & 1u))       c_[nt][0] -= MPEN;
                    if (!((w0 >> (bit + 1)) & 1u)) c_[nt][1] -= MPEN;
                    if (!((w1 >> bit) & 1u))       c_[nt][2] -= MPEN;
                    if (!((w1 >> (bit + 1)) & 1u)) c_[nt][3] -= MPEN;
                }
            }
        }

        // ---- softmax: p = 2^z in fp16x2 (global 2^-ZOFF scale cancels in normalize) ----
        uint32_t ph[2][4];
        #pragma unroll
        for (int kk = 0; kk < 2; kk++) {
            ph[kk][0] = packf16(c_[2*kk][0],     c_[2*kk][1]);
            ph[kk][1] = packf16(c_[2*kk][2],     c_[2*kk][3]);
            ph[kk][2] = packf16(c_[2*kk + 1][0], c_[2*kk + 1][1]);
            ph[kk][3] = packf16(c_[2*kk + 1][2], c_[2*kk + 1][3]);
            ex2h2(ph[kk][0]); ex2h2(ph[kk][1]); ex2h2(ph[kk][2]); ex2h2(ph[kk][3]);
        }

        // ---- O += P * V ; l via ones-column (d64) ----
        #pragma unroll
        for (int kk = 0; kk < 2; kk++) {
            #pragma unroll
            for (int p = 0; p < 4; p++) {
                uint32_t a = stb + VH_OFF + (uint32_t)(kk * (16 * VSTR))
                           + (uint32_t)(p * 32) + vfoff;
                uint32_t v0, v1, v2, v3;
                ldm4t(v0, v1, v2, v3, a);
                mma16816(Oa[2*p],     ph[kk], v0, v1);
                mma16816(Oa[2*p + 1], ph[kk], v2, v3);
            }
            {
                uint32_t a = stb + VH_OFF + (uint32_t)(kk * (16 * VSTR))
                           + (uint32_t)(4 * 32) + vfoff;
                uint32_t v0, v1;
                ldm2t(v0, v1, a);
                mma16816(Ol, ph[kk], v0, v1);
            }
        }

        CP_WAIT1();
        GBAR();

        comp_off += STAGE_BYTES; if (comp_off == NSTAGE * STAGE_BYTES) comp_off = 0;
        fill_off += STAGE_BYTES; if (fill_off == NSTAGE * STAGE_BYTES) fill_off = 0;
    }

    // ---- l lives in the d64 column (tg==0 lanes); broadcast within each quad ----
    float l0 = __shfl_sync(0xffffffffu, Ol[0], lane & ~3);
    float l1 = __shfl_sync(0xffffffffu, Ol[2], lane & ~3);

    __syncthreads();   // join groups; both done reading stages before smem reuse

    float* sOut = (float*)smbuf;                                // [64][72] fp32
    float* sL   = (float*)(smbuf + NSTAGE * STAGE_BYTES);       // [64] fp32
    const int rloc1 = rloc0 + 8;

    if (wg == 0) {
        #pragma unroll
        for (int nd = 0; nd < 8; nd++) {
            int col = nd * 8 + 2 * tg;
            *(float2*)&sOut[rloc0 * 72 + col] = make_float2(Oa[nd][0], Oa[nd][1]);
            *(float2*)&sOut[rloc1 * 72 + col] = make_float2(Oa[nd][2], Oa[nd][3]);
        }
        if (tg == 0) { sL[rloc0] = l0; sL[rloc1] = l1; }
    }
    __syncthreads();
    if (wg == 1) {
        float inv0 = 1.0f / (l0 + sL[rloc0]);
        float inv1 = 1.0f / (l1 + sL[rloc1]);
        float* o0 = O + ((size_t)((b * Hh + h) * Ll) + r0g) * Ee;
        float* o1 = o0 + (size_t)8 * Ee;
        #pragma unroll
        for (int nd = 0; nd < 8; nd++) {
            int col = nd * 8 + 2 * tg;
            float2 a0 = *(float2*)&sOut[rloc0 * 72 + col];
            float2 a1 = *(float2*)&sOut[rloc1 * 72 + col];
            *(float2*)(o0 + col) = make_float2((Oa[nd][0] + a0.x) * inv0,
                                               (Oa[nd][1] + a0.y) * inv0);
            *(float2*)(o1 + col) = make_float2((Oa[nd][2] + a1.x) * inv1,
                                               (Oa[nd][3] + a1.y) * inv1);
        }
    }
    #undef GBAR
}

extern "C" void kernel_launch(void* const* d_in, const int* in_sizes, int n_in,
                              void* d_out, int out_size)
{
    const float* Q = (const float*)d_in[0];
    const float* K = (const float*)d_in[1];
    const float* V = (const float*)d_in[2];
    const float* M = (const float*)d_in[3];
    float* O = (float*)d_out;

    prep_kernel<<<4096, 256>>>(M, K, V);

    cudaFuncSetAttribute(fa_mma_kernel, cudaFuncAttributeMaxDynamicSharedMemorySize, SM_BYTES);
    dim3 grid(Ll / BM, Hh, Bb);
    fa_mma_kernel<<<grid, 256, SM_BYTES>>>(Q, O);
}

// round 15
// speedup vs baseline: 1.2530x; 1.1595x over previous
#include <cuda_runtime.h>
#include <cstdint>

#define Bb   2
#define Ll   2048
#define Ssz  2048
#define Hh   16
#define Ee   64
#define BN   64
#define BM   64
#define NTIL (Ssz / BN)          // 32
#define C0   0.18033688011112042f    // 0.125 * log2(e)
#define MPEN 1.8033688011112042e8f   // 1e9 * C0 (finite mask penalty, matches reference)

// one stage: K fp16 [64 s][144B] + V fp16 [64 s][176B] (d 0..63 data, d64=1.0 ones col)
#define KH_OFF 0
#define VH_OFF 9216
#define VSTR   176
#define STAGE_BYTES 20480
#define NSTAGE 3
#define SM_BYTES (NSTAGE * STAGE_BYTES + 640)   // 62080 per CTA; x2 CTAs <= 228KB

__device__ unsigned int g_maskbits[(size_t)Bb * Ll * (Ssz / 32)];
// fp16 K/V, head-major [b,h,s,e], packed 2 per uint32
__device__ uint32_t g_kh[(size_t)Bb * Hh * Ssz * Ee / 2];
__device__ uint32_t g_vh[(size_t)Bb * Hh * Ssz * Ee / 2];

__device__ __forceinline__ uint32_t smem_u32(const void* p) {
    uint32_t a;
    asm("{ .reg .u64 t; cvta.to.shared.u64 t, %1; cvt.u32.u64 %0, t; }" : "=r"(a) : "l"(p));
    return a;
}
__device__ __forceinline__ uint32_t packf16(float lo, float hi) {   // low 16 bits <- lo
    uint32_t r; asm("cvt.rn.f16x2.f32 %0, %1, %2;" : "=r"(r) : "f"(hi), "f"(lo)); return r;
}
__device__ __forceinline__ void ex2h2(uint32_t& x) {
    asm("ex2.approx.f16x2 %0, %0;" : "+r"(x));
}
__device__ __forceinline__ void ldm4(uint32_t& r0, uint32_t& r1, uint32_t& r2, uint32_t& r3,
                                     uint32_t a) {
    asm volatile("ldmatrix.sync.aligned.m8n8.x4.shared.b16 {%0,%1,%2,%3}, [%4];"
                 : "=r"(r0), "=r"(r1), "=r"(r2), "=r"(r3) : "r"(a));
}
__device__ __forceinline__ void ldm4t(uint32_t& r0, uint32_t& r1, uint32_t& r2, uint32_t& r3,
                                      uint32_t a) {
    asm volatile("ldmatrix.sync.aligned.m8n8.x4.trans.shared.b16 {%0,%1,%2,%3}, [%4];"
                 : "=r"(r0), "=r"(r1), "=r"(r2), "=r"(r3) : "r"(a));
}
__device__ __forceinline__ void ldm2t(uint32_t& r0, uint32_t& r1, uint32_t a) {
    asm volatile("ldmatrix.sync.aligned.m8n8.x2.trans.shared.b16 {%0,%1}, [%2];"
                 : "=r"(r0), "=r"(r1) : "r"(a));
}
__device__ __forceinline__ void mma16816(float* c, const uint32_t* a, uint32_t b0, uint32_t b1) {
    asm volatile("mma.sync.aligned.m16n8k16.row.col.f32.f16.f16.f32 "
                 "{%0,%1,%2,%3},{%4,%5,%6,%7},{%8,%9},{%0,%1,%2,%3};"
                 : "+f"(c[0]), "+f"(c[1]), "+f"(c[2]), "+f"(c[3])
                 : "r"(a[0]), "r"(a[1]), "r"(a[2]), "r"(a[3]), "r"(b0), "r"(b1));
}
__device__ __forceinline__ void g_load8(const float* p, float* r) {
    float4 a = ((const float4*)p)[0];
    float4 b = ((const float4*)p)[1];
    r[0] = a.x; r[1] = a.y; r[2] = a.z; r[3] = a.w;
    r[4] = b.x; r[5] = b.y; r[6] = b.z; r[7] = b.w;
}
#define CP16(dst, src) asm volatile("cp.async.cg.shared.global [%0], [%1], 16;" \
                                    :: "r"(dst), "l"(src) : "memory")
#define CP_COMMIT() asm volatile("cp.async.commit_group;" ::: "memory")
#define CP_WAIT1()  asm volatile("cp.async.wait_group 1;" ::: "memory")

// ---- fused pre-pass: blocks [0,2048) -> maskbits, [2048,4096) -> K/V fp16 convert ----
__global__ void prep_kernel(const float* __restrict__ msk,
                            const float* __restrict__ K, const float* __restrict__ V) {
    if (blockIdx.x < 2048) {
        const int T = blockIdx.x * 256 + threadIdx.x;
        const float4* p = (const float4*)(msk + (size_t)T * 16);
        float4 v0 = p[0], v1 = p[1], v2 = p[2], v3 = p[3];
        uint32_t bits = 0;
        bits |= (v0.x > 0.5f) ? 1u : 0u;        bits |= (v0.y > 0.5f) ? 2u : 0u;
        bits |= (v0.z > 0.5f) ? 4u : 0u;        bits |= (v0.w > 0.5f) ? 8u : 0u;
        bits |= (v1.x > 0.5f) ? 16u : 0u;       bits |= (v1.y > 0.5f) ? 32u : 0u;
        bits |= (v1.z > 0.5f) ? 64u : 0u;       bits |= (v1.w > 0.5f) ? 128u : 0u;
        bits |= (v2.x > 0.5f) ? 256u : 0u;      bits |= (v2.y > 0.5f) ? 512u : 0u;
        bits |= (v2.z > 0.5f) ? 1024u : 0u;     bits |= (v2.w > 0.5f) ? 2048u : 0u;
        bits |= (v3.x > 0.5f) ? 4096u : 0u;     bits |= (v3.y > 0.5f) ? 8192u : 0u;
        bits |= (v3.z > 0.5f) ? 16384u : 0u;    bits |= (v3.w > 0.5f) ? 32768u : 0u;
        uint32_t x = bits << (16 * (T & 1));
        x |= __shfl_xor_sync(0xffffffffu, x, 1);
        if (!(T & 1)) g_maskbits[T >> 1] = x;
    } else {
        size_t idx = (size_t)(blockIdx.x - 2048) * 256 + threadIdx.x;
        int c = (int)(idx & 7);
        int s = (int)((idx >> 3) & (Ssz - 1));
        int h = (int)((idx >> 14) & (Hh - 1));
        int b = (int)(idx >> 18);
        size_t src = (((size_t)b * Ssz + s) * Hh + h) * Ee + c * 8;
        size_t dst4 = ((((size_t)b * Hh + h) * Ssz + s) * Ee + c * 8) >> 1;
        float kr[8], vr[8];
        g_load8(K + src, kr);
        g_load8(V + src, vr);
        uint4 ko = make_uint4(packf16(kr[0], kr[1]), packf16(kr[2], kr[3]),
                              packf16(kr[4], kr[5]), packf16(kr[6], kr[7]));
        uint4 vo = make_uint4(packf16(vr[0], vr[1]), packf16(vr[2], vr[3]),
                              packf16(vr[4], vr[5]), packf16(vr[6], vr[7]));
        *(uint4*)&g_kh[dst4] = ko;
        *(uint4*)&g_vh[dst4] = vo;
    }
}

__global__ __launch_bounds__(256, 2)
void fa_mma_kernel(const float* __restrict__ Q, float* __restrict__ O)
{
    extern __shared__ char smbuf[];
    const uint32_t sb = smem_u32(smbuf);

    const int tid  = threadIdx.x;
    const int wid  = tid >> 5;
    const int lane = tid & 31;
    const int wg   = wid >> 2;          // n-half: 0 -> keys [0,32), 1 -> [32,64)
    const int wm   = wid & 3;           // row group: rows wm*16 .. wm*16+15
    const int g    = lane >> 2;
    const int tg   = lane & 3;
    const int mtile = blockIdx.x, h = blockIdx.y, b = blockIdx.z;
    const int rloc0 = wm * 16 + g;
    const int r0g   = mtile * BM + rloc0;

    const int bar_id = 1 + wg;
    #define GBAR() asm volatile("bar.sync %0, 128;" :: "r"(bar_id) : "memory")

    // ---- stage Q (scaled by C0) as single fp16 into smem (256 thr: 16 floats each) ----
    {
        const int row = tid >> 2, dh = tid & 3;
        const float* qg = Q + ((size_t)(b * Ll + mtile * BM + row) * Hh + h) * Ee + dh * 16;
        float qv[16];
        g_load8(qg, qv);
        g_load8(qg + 8, qv + 8);
        uint32_t hw[8];
        #pragma unroll
        for (int i = 0; i < 8; i++) hw[i] = packf16(qv[2*i] * C0, qv[2*i+1] * C0);
        char* qh_dst = smbuf + row * 144 + dh * 32;
        ((uint4*)qh_dst)[0] = make_uint4(hw[0], hw[1], hw[2], hw[3]);
        ((uint4*)qh_dst)[1] = make_uint4(hw[4], hw[5], hw[6], hw[7]);
    }
    __syncthreads();

    uint32_t qh[4][4];
    {
        uint32_t qoff = (uint32_t)((wm * 16 + ((lane >> 3) & 1) * 8 + (lane & 7)) * 144
                                   + (lane >> 4) * 16);
        #pragma unroll
        for (int kk = 0; kk < 4; kk++)
            ldm4(qh[kk][0], qh[kk][1], qh[kk][2], qh[kk][3], sb + qoff + kk * 32);
    }
    __syncthreads();   // Q consumed; smem free for K/V stages

    // fragment offsets
    const uint32_t kfoff = (uint32_t)((((lane >> 4) * 8 + (lane & 7)) * 144)
                                      + ((lane >> 3) & 1) * 16 + wg * 4608);
    const uint32_t vfoff = (uint32_t)((((lane & 7) + ((lane >> 3) & 1) * 8) * VSTR)
                                      + (lane >> 4) * 16 + wg * (32 * VSTR));

    // cp.async fill: thread -> row frow=tid>>2 (0..63), chunks fc2,fc2+1 (16B each).
    const int frow = tid >> 2, fc2 = (tid & 3) * 2;
    const char* KhB = (const char*)g_kh + ((((size_t)b * Hh + h) * Ssz + frow) * Ee + fc2 * 8) * 2;
    const char* VhB = (const char*)g_vh + ((((size_t)b * Hh + h) * Ssz + frow) * Ee + fc2 * 8) * 2;
    const uint32_t fdstK = (uint32_t)(frow * 144 + fc2 * 16);
    const uint32_t fdstV = (uint32_t)(frow * VSTR + fc2 * 16);

    // ---- V pad word at +128 per row: d64 = fp16 1.0 (ones column for l-sum) ----
    {
        const int pr = tid >> 2, pw = tid & 3;
        uint32_t val = (pw == 0) ? 0x00003C00u : 0u;
        #pragma unroll
        for (int st = 0; st < NSTAGE; st++)
            *(uint32_t*)(smbuf + st * STAGE_BYTES + VH_OFF + pr * VSTR + 128 + pw * 4) = val;
    }

    // ---- prologue: fill stages 0,1 with tiles 0,1 ----
    CP16(sb + KH_OFF + fdstK, KhB);
    CP16(sb + KH_OFF + fdstK + 16, KhB + 16);
    CP16(sb + VH_OFF + fdstV, VhB);
    CP16(sb + VH_OFF + fdstV + 16, VhB + 16);
    CP_COMMIT();
    {
        size_t goff = (size_t)BN * Ee * 2;
        CP16(sb + STAGE_BYTES + KH_OFF + fdstK, KhB + goff);
        CP16(sb + STAGE_BYTES + KH_OFF + fdstK + 16, KhB + goff + 16);
        CP16(sb + STAGE_BYTES + VH_OFF + fdstV, VhB + goff);
        CP16(sb + STAGE_BYTES + VH_OFF + fdstV + 16, VhB + goff + 16);
    }
    CP_COMMIT();
    CP_WAIT1();    // tile 0 landed
    GBAR();

    float Oa[8][4];
    #pragma unroll
    for (int nd = 0; nd < 8; nd++)
        #pragma unroll
        for (int j = 0; j < 4; j++) Oa[nd][j] = 0.0f;
    float Ol[4] = {0.0f, 0.0f, 0.0f, 0.0f};

    const size_t mrow0 = ((size_t)(b * Ll + r0g)) * (Ssz / 32);
    const size_t mrow1 = mrow0 + 8 * (Ssz / 32);

    uint32_t comp_off = 0;
    uint32_t fill_off = 2 * STAGE_BYTES;

    for (int t = 0; t < NTIL; t++) {
        if (t + 2 < NTIL) {
            const uint32_t stn = sb + fill_off;
            size_t goff = (size_t)(t + 2) * BN * Ee * 2;
            CP16(stn + KH_OFF + fdstK, KhB + goff);
            CP16(stn + KH_OFF + fdstK + 16, KhB + goff + 16);
            CP16(stn + VH_OFF + fdstV, VhB + goff);
            CP16(stn + VH_OFF + fdstV + 16, VhB + goff + 16);
        }
        CP_COMMIT();

        const uint32_t stb = sb + comp_off;

        // ---- S = q_fp16 * K  (single-term; Q quant noise ~2.8e-4, inside budget) ----
        float c_[4][4];
        #pragma unroll
        for (int nt = 0; nt < 4; nt++)
            #pragma unroll
            for (int j = 0; j < 4; j++) c_[nt][j] = 0.0f;

        #pragma unroll
        for (int kk = 0; kk < 4; kk++) {
            #pragma unroll
            for (int p = 0; p < 2; p++) {
                uint32_t a = stb + KH_OFF + (uint32_t)(p * 2304) + (uint32_t)(kk * 32) + kfoff;
                uint32_t k0, k1, k2, k3;
                ldm4(k0, k1, k2, k3, a);
                mma16816(c_[2*p],     qh[kk], k0, k1);
                mma16816(c_[2*p + 1], qh[kk], k2, k3);
            }
        }

        // ---- mask (one word per row per tile-half; all-ones fast path) ----
        {
            uint32_t w0 = g_maskbits[mrow0 + t * 2 + wg];
            uint32_t w1 = g_maskbits[mrow1 + t * 2 + wg];
            if ((w0 & w1) != 0xFFFFFFFFu) {
                #pragma unroll
                for (int nt = 0; nt < 4; nt++) {
                    int bit = nt * 8 + 2 * tg;
                    if (!((w0 >> bit) & 1u))       c_[nt][0] -= MPEN;
                    if (!((w0 >> (bit + 1)) & 1u)) c_[nt][1] -= MPEN;
                    if (!((w1 >> bit) & 1u))       c_[nt][2] -= MPEN;
                    if (!((w1 >> (bit + 1)) & 1u)) c_[nt][3] -= MPEN;
                }
            }
        }

        // ---- softmax: p = 2^z in fp16x2 (global scale cancels in normalize) ----
        uint32_t ph[2][4];
        #pragma unroll
        for (int kk = 0; kk < 2; kk++) {
            ph[kk][0] = packf16(c_[2*kk][0],     c_[2*kk][1]);
            ph[kk][1] = packf16(c_[2*kk][2],     c_[2*kk][3]);
            ph[kk][2] = packf16(c_[2*kk + 1][0], c_[2*kk + 1][1]);
            ph[kk][3] = packf16(c_[2*kk + 1][2], c_[2*kk + 1][3]);
            ex2h2(ph[kk][0]); ex2h2(ph[kk][1]); ex2h2(ph[kk][2]); ex2h2(ph[kk][3]);
        }

        // ---- O += P * V ; l via ones-column (d64) ----
        #pragma unroll
        for (int kk = 0; kk < 2; kk++) {
            #pragma unroll
            for (int p = 0; p < 4; p++) {
                uint32_t a = stb + VH_OFF + (uint32_t)(kk * (16 * VSTR))
                           + (uint32_t)(p * 32) + vfoff;
                uint32_t v0, v1, v2, v3;
                ldm4t(v0, v1, v2, v3, a);
                mma16816(Oa[2*p],     ph[kk], v0, v1);
                mma16816(Oa[2*p + 1], ph[kk], v2, v3);
            }
            {
                uint32_t a = stb + VH_OFF + (uint32_t)(kk * (16 * VSTR))
                           + (uint32_t)(4 * 32) + vfoff;
                uint32_t v0, v1;
                ldm2t(v0, v1, a);
                mma16816(Ol, ph[kk], v0, v1);
            }
        }

        CP_WAIT1();
        GBAR();

        comp_off += STAGE_BYTES; if (comp_off == NSTAGE * STAGE_BYTES) comp_off = 0;
        fill_off += STAGE_BYTES; if (fill_off == NSTAGE * STAGE_BYTES) fill_off = 0;
    }

    // ---- l lives in the d64 column (tg==0 lanes); broadcast within each quad ----
    float l0 = __shfl_sync(0xffffffffu, Ol[0], lane & ~3);
    float l1 = __shfl_sync(0xffffffffu, Ol[2], lane & ~3);

    __syncthreads();   // join groups; both done reading stages before smem reuse

    float* sOut = (float*)smbuf;                                // [64][72] fp32
    float* sL   = (float*)(smbuf + NSTAGE * STAGE_BYTES);       // [64] fp32
    const int rloc1 = rloc0 + 8;

    if (wg == 0) {
        #pragma unroll
        for (int nd = 0; nd < 8; nd++) {
            int col = nd * 8 + 2 * tg;
            *(float2*)&sOut[rloc0 * 72 + col] = make_float2(Oa[nd][0], Oa[nd][1]);
            *(float2*)&sOut[rloc1 * 72 + col] = make_float2(Oa[nd][2], Oa[nd][3]);
        }
        if (tg == 0) { sL[rloc0] = l0; sL[rloc1] = l1; }
    }
    __syncthreads();
    if (wg == 1) {
        float inv0 = 1.0f / (l0 + sL[rloc0]);
        float inv1 = 1.0f / (l1 + sL[rloc1]);
        float* o0 = O + ((size_t)((b * Hh + h) * Ll) + r0g) * Ee;
        float* o1 = o0 + (size_t)8 * Ee;
        #pragma unroll
        for (int nd = 0; nd < 8; nd++) {
            int col = nd * 8 + 2 * tg;
            float2 a0 = *(float2*)&sOut[rloc0 * 72 + col];
            float2 a1 = *(float2*)&sOut[rloc1 * 72 + col];
            *(float2*)(o0 + col) = make_float2((Oa[nd][0] + a0.x) * inv0,
                                               (Oa[nd][1] + a0.y) * inv0);
            *(float2*)(o1 + col) = make_float2((Oa[nd][2] + a1.x) * inv1,
                                               (Oa[nd][3] + a1.y) * inv1);
        }
    }
    #undef GBAR
}

extern "C" void kernel_launch(void* const* d_in, const int* in_sizes, int n_in,
                              void* d_out, int out_size)
{
    const float* Q = (const float*)d_in[0];
    const float* K = (const float*)d_in[1];
    const float* V = (const float*)d_in[2];
    const float* M = (const float*)d_in[3];
    float* O = (float*)d_out;

    prep_kernel<<<4096, 256>>>(M, K, V);

    cudaFuncSetAttribute(fa_mma_kernel, cudaFuncAttributeMaxDynamicSharedMemorySize, SM_BYTES);
    dim3 grid(Ll / BM, Hh, Bb);
    fa_mma_kernel<<<grid, 256, SM_BYTES>>>(Q, O);
}

// round 16
// speedup vs baseline: 1.2712x; 1.0146x over previous
#include <cuda_runtime.h>
#include <cstdint>

#define Bb   2
#define Ll   2048
#define Ssz  2048
#define Hh   16
#define Ee   64
#define BN   64
#define BM   64
#define NTIL (Ssz / BN)          // 32
#define C0   0.18033688011112042f    // 0.125 * log2(e)
#define MPEN 1.8033688011112042e8f   // 1e9 * C0 (finite mask penalty, matches reference)

// one stage: K fp16 [64 s][144B] + V fp16 [64 s][144B]
#define KH_OFF 0
#define VH_OFF 9216
#define VSTR   144
#define STAGE_BYTES 18432
#define NSTAGE 4
#define SM_BYTES (NSTAGE * STAGE_BYTES + 640)   // 74368 per CTA; x2 CTAs = 148736 <= 228KB

__device__ unsigned int g_maskbits[(size_t)Bb * Ll * (Ssz / 32)];
// fp16 K/V, head-major [b,h,s,e], packed 2 per uint32
__device__ uint32_t g_kh[(size_t)Bb * Hh * Ssz * Ee / 2];
__device__ uint32_t g_vh[(size_t)Bb * Hh * Ssz * Ee / 2];

__device__ __forceinline__ uint32_t smem_u32(const void* p) {
    uint32_t a;
    asm("{ .reg .u64 t; cvta.to.shared.u64 t, %1; cvt.u32.u64 %0, t; }" : "=r"(a) : "l"(p));
    return a;
}
__device__ __forceinline__ uint32_t packf16(float lo, float hi) {   // low 16 bits <- lo
    uint32_t r; asm("cvt.rn.f16x2.f32 %0, %1, %2;" : "=r"(r) : "f"(hi), "f"(lo)); return r;
}
__device__ __forceinline__ void unpkf16(uint32_t w, float& a, float& b) {
    asm("{ .reg .b16 l,h; mov.b32 {l,h}, %2; cvt.f32.f16 %0, l; cvt.f32.f16 %1, h; }"
        : "=f"(a), "=f"(b) : "r"(w));
}
__device__ __forceinline__ void ex2h2(uint32_t& x) {
    asm("ex2.approx.f16x2 %0, %0;" : "+r"(x));
}
__device__ __forceinline__ void ldm4(uint32_t& r0, uint32_t& r1, uint32_t& r2, uint32_t& r3,
                                     uint32_t a) {
    asm volatile("ldmatrix.sync.aligned.m8n8.x4.shared.b16 {%0,%1,%2,%3}, [%4];"
                 : "=r"(r0), "=r"(r1), "=r"(r2), "=r"(r3) : "r"(a));
}
__device__ __forceinline__ void ldm4t(uint32_t& r0, uint32_t& r1, uint32_t& r2, uint32_t& r3,
                                      uint32_t a) {
    asm volatile("ldmatrix.sync.aligned.m8n8.x4.trans.shared.b16 {%0,%1,%2,%3}, [%4];"
                 : "=r"(r0), "=r"(r1), "=r"(r2), "=r"(r3) : "r"(a));
}
__device__ __forceinline__ void mma16816(float* c, const uint32_t* a, uint32_t b0, uint32_t b1) {
    asm volatile("mma.sync.aligned.m16n8k16.row.col.f32.f16.f16.f32 "
                 "{%0,%1,%2,%3},{%4,%5,%6,%7},{%8,%9},{%0,%1,%2,%3};"
                 : "+f"(c[0]), "+f"(c[1]), "+f"(c[2]), "+f"(c[3])
                 : "r"(a[0]), "r"(a[1]), "r"(a[2]), "r"(a[3]), "r"(b0), "r"(b1));
}
__device__ __forceinline__ void g_load8(const float* p, float* r) {
    float4 a = ((const float4*)p)[0];
    float4 b = ((const float4*)p)[1];
    r[0] = a.x; r[1] = a.y; r[2] = a.z; r[3] = a.w;
    r[4] = b.x; r[5] = b.y; r[6] = b.z; r[7] = b.w;
}
#define CP16(dst, src) asm volatile("cp.async.cg.shared.global [%0], [%1], 16;" \
                                    :: "r"(dst), "l"(src) : "memory")
#define CP_COMMIT() asm volatile("cp.async.commit_group;" ::: "memory")
#define CP_WAIT2()  asm volatile("cp.async.wait_group 2;" ::: "memory")

// ---- fused pre-pass: blocks [0,2048) -> maskbits, [2048,4096) -> K/V fp16 convert ----
__global__ void prep_kernel(const float* __restrict__ msk,
                            const float* __restrict__ K, const float* __restrict__ V) {
    if (blockIdx.x < 2048) {
        const int T = blockIdx.x * 256 + threadIdx.x;
        const float4* p = (const float4*)(msk + (size_t)T * 16);
        float4 v0 = p[0], v1 = p[1], v2 = p[2], v3 = p[3];
        uint32_t bits = 0;
        bits |= (v0.x > 0.5f) ? 1u : 0u;        bits |= (v0.y > 0.5f) ? 2u : 0u;
        bits |= (v0.z > 0.5f) ? 4u : 0u;        bits |= (v0.w > 0.5f) ? 8u : 0u;
        bits |= (v1.x > 0.5f) ? 16u : 0u;       bits |= (v1.y > 0.5f) ? 32u : 0u;
        bits |= (v1.z > 0.5f) ? 64u : 0u;       bits |= (v1.w > 0.5f) ? 128u : 0u;
        bits |= (v2.x > 0.5f) ? 256u : 0u;      bits |= (v2.y > 0.5f) ? 512u : 0u;
        bits |= (v2.z > 0.5f) ? 1024u : 0u;     bits |= (v2.w > 0.5f) ? 2048u : 0u;
        bits |= (v3.x > 0.5f) ? 4096u : 0u;     bits |= (v3.y > 0.5f) ? 8192u : 0u;
        bits |= (v3.z > 0.5f) ? 16384u : 0u;    bits |= (v3.w > 0.5f) ? 32768u : 0u;
        uint32_t x = bits << (16 * (T & 1));
        x |= __shfl_xor_sync(0xffffffffu, x, 1);
        if (!(T & 1)) g_maskbits[T >> 1] = x;
    } else {
        size_t idx = (size_t)(blockIdx.x - 2048) * 256 + threadIdx.x;
        int c = (int)(idx & 7);
        int s = (int)((idx >> 3) & (Ssz - 1));
        int h = (int)((idx >> 14) & (Hh - 1));
        int b = (int)(idx >> 18);
        size_t src = (((size_t)b * Ssz + s) * Hh + h) * Ee + c * 8;
        size_t dst4 = ((((size_t)b * Hh + h) * Ssz + s) * Ee + c * 8) >> 1;
        float kr[8], vr[8];
        g_load8(K + src, kr);
        g_load8(V + src, vr);
        uint4 ko = make_uint4(packf16(kr[0], kr[1]), packf16(kr[2], kr[3]),
                              packf16(kr[4], kr[5]), packf16(kr[6], kr[7]));
        uint4 vo = make_uint4(packf16(vr[0], vr[1]), packf16(vr[2], vr[3]),
                              packf16(vr[4], vr[5]), packf16(vr[6], vr[7]));
        *(uint4*)&g_kh[dst4] = ko;
        *(uint4*)&g_vh[dst4] = vo;
    }
}

__global__ __launch_bounds__(256, 2)
void fa_mma_kernel(const float* __restrict__ Q, float* __restrict__ O)
{
    extern __shared__ char smbuf[];
    const uint32_t sb = smem_u32(smbuf);

    const int tid  = threadIdx.x;
    const int wid  = tid >> 5;
    const int lane = tid & 31;
    const int wg   = wid >> 2;          // n-half: 0 -> keys [0,32), 1 -> [32,64)
    const int wm   = wid & 3;           // row group: rows wm*16 .. wm*16+15
    const int g    = lane >> 2;
    const int tg   = lane & 3;
    const int mtile = blockIdx.x, h = blockIdx.y, b = blockIdx.z;
    const int rloc0 = wm * 16 + g;
    const int r0g   = mtile * BM + rloc0;

    const int bar_id = 1 + wg;
    #define GBAR() asm volatile("bar.sync %0, 128;" :: "r"(bar_id) : "memory")

    // ---- stage Q (scaled by C0) as single fp16 into smem (256 thr: 16 floats each) ----
    {
        const int row = tid >> 2, dh = tid & 3;
        const float* qg = Q + ((size_t)(b * Ll + mtile * BM + row) * Hh + h) * Ee + dh * 16;
        float qv[16];
        g_load8(qg, qv);
        g_load8(qg + 8, qv + 8);
        uint32_t hw[8];
        #pragma unroll
        for (int i = 0; i < 8; i++) hw[i] = packf16(qv[2*i] * C0, qv[2*i+1] * C0);
        char* qh_dst = smbuf + row * 144 + dh * 32;
        ((uint4*)qh_dst)[0] = make_uint4(hw[0], hw[1], hw[2], hw[3]);
        ((uint4*)qh_dst)[1] = make_uint4(hw[4], hw[5], hw[6], hw[7]);
    }
    __syncthreads();

    uint32_t qh[4][4];
    {
        uint32_t qoff = (uint32_t)((wm * 16 + ((lane >> 3) & 1) * 8 + (lane & 7)) * 144
                                   + (lane >> 4) * 16);
        #pragma unroll
        for (int kk = 0; kk < 4; kk++)
            ldm4(qh[kk][0], qh[kk][1], qh[kk][2], qh[kk][3], sb + qoff + kk * 32);
    }
    __syncthreads();   // Q consumed; smem free for K/V stages

    // fragment offsets
    const uint32_t kfoff = (uint32_t)((((lane >> 4) * 8 + (lane & 7)) * 144)
                                      + ((lane >> 3) & 1) * 16 + wg * 4608);
    const uint32_t vfoff = (uint32_t)((((lane & 7) + ((lane >> 3) & 1) * 8) * VSTR)
                                      + (lane >> 4) * 16 + wg * (32 * VSTR));

    // cp.async fill: thread -> row frow=tid>>2 (0..63), chunks fc2,fc2+1 (16B each).
    const int frow = tid >> 2, fc2 = (tid & 3) * 2;
    const char* KhB = (const char*)g_kh + ((((size_t)b * Hh + h) * Ssz + frow) * Ee + fc2 * 8) * 2;
    const char* VhB = (const char*)g_vh + ((((size_t)b * Hh + h) * Ssz + frow) * Ee + fc2 * 8) * 2;
    const uint32_t fdstK = (uint32_t)(frow * 144 + fc2 * 16);
    const uint32_t fdstV = (uint32_t)(frow * VSTR + fc2 * 16);

    // ---- prologue: fill stages 0,1,2 with tiles 0,1,2 ----
    #pragma unroll
    for (int pt = 0; pt < 3; pt++) {
        size_t goff = (size_t)pt * BN * Ee * 2;
        uint32_t stp = sb + (uint32_t)(pt * STAGE_BYTES);
        CP16(stp + KH_OFF + fdstK, KhB + goff);
        CP16(stp + KH_OFF + fdstK + 16, KhB + goff + 16);
        CP16(stp + VH_OFF + fdstV, VhB + goff);
        CP16(stp + VH_OFF + fdstV + 16, VhB + goff + 16);
        CP_COMMIT();
    }
    CP_WAIT2();    // tile 0 landed
    GBAR();

    float Oa[8][4];
    #pragma unroll
    for (int nd = 0; nd < 8; nd++)
        #pragma unroll
        for (int j = 0; j < 4; j++) Oa[nd][j] = 0.0f;
    float l0 = 0.0f, l1 = 0.0f;

    const size_t mrow0 = ((size_t)(b * Ll + r0g)) * (Ssz / 32);
    const size_t mrow1 = mrow0 + 8 * (Ssz / 32);

    uint32_t comp_off = 0;
    uint32_t fill_off = 3 * STAGE_BYTES;

    for (int t = 0; t < NTIL; t++) {
        if (t + 3 < NTIL) {
            const uint32_t stn = sb + fill_off;
            size_t goff = (size_t)(t + 3) * BN * Ee * 2;
            CP16(stn + KH_OFF + fdstK, KhB + goff);
            CP16(stn + KH_OFF + fdstK + 16, KhB + goff + 16);
            CP16(stn + VH_OFF + fdstV, VhB + goff);
            CP16(stn + VH_OFF + fdstV + 16, VhB + goff + 16);
        }
        CP_COMMIT();

        const uint32_t stb = sb + comp_off;

        // ---- S = q_fp16 * K ----
        float c_[4][4];
        #pragma unroll
        for (int nt = 0; nt < 4; nt++)
            #pragma unroll
            for (int j = 0; j < 4; j++) c_[nt][j] = 0.0f;

        #pragma unroll
        for (int kk = 0; kk < 4; kk++) {
            #pragma unroll
            for (int p = 0; p < 2; p++) {
                uint32_t a = stb + KH_OFF + (uint32_t)(p * 2304) + (uint32_t)(kk * 32) + kfoff;
                uint32_t k0, k1, k2, k3;
                ldm4(k0, k1, k2, k3, a);
                mma16816(c_[2*p],     qh[kk], k0, k1);
                mma16816(c_[2*p + 1], qh[kk], k2, k3);
            }
        }

        // ---- mask (one word per row per tile-half; all-ones fast path) ----
        {
            uint32_t w0 = g_maskbits[mrow0 + t * 2 + wg];
            uint32_t w1 = g_maskbits[mrow1 + t * 2 + wg];
            if ((w0 & w1) != 0xFFFFFFFFu) {
                #pragma unroll
                for (int nt = 0; nt < 4; nt++) {
                    int bit = nt * 8 + 2 * tg;
                    if (!((w0 >> bit) & 1u))       c_[nt][0] -= MPEN;
                    if (!((w0 >> (bit + 1)) & 1u)) c_[nt][1] -= MPEN;
                    if (!((w1 >> bit) & 1u))       c_[nt][2] -= MPEN;
                    if (!((w1 >> (bit + 1)) & 1u)) c_[nt][3] -= MPEN;
                }
            }
        }

        // ---- softmax: p = 2^z in fp16x2 (global scale cancels in normalize) ----
        uint32_t ph[2][4];
        #pragma unroll
        for (int kk = 0; kk < 2; kk++) {
            ph[kk][0] = packf16(c_[2*kk][0],     c_[2*kk][1]);
            ph[kk][1] = packf16(c_[2*kk][2],     c_[2*kk][3]);
            ph[kk][2] = packf16(c_[2*kk + 1][0], c_[2*kk + 1][1]);
            ph[kk][3] = packf16(c_[2*kk + 1][2], c_[2*kk + 1][3]);
            ex2h2(ph[kk][0]); ex2h2(ph[kk][1]); ex2h2(ph[kk][2]); ex2h2(ph[kk][3]);
        }

        // ---- O += P * V ----
        #pragma unroll
        for (int kk = 0; kk < 2; kk++) {
            #pragma unroll
            for (int p = 0; p < 4; p++) {
                uint32_t a = stb + VH_OFF + (uint32_t)(kk * (16 * VSTR))
                           + (uint32_t)(p * 32) + vfoff;
                uint32_t v0, v1, v2, v3;
                ldm4t(v0, v1, v2, v3, a);
                mma16816(Oa[2*p],     ph[kk], v0, v1);
                mma16816(Oa[2*p + 1], ph[kk], v2, v3);
            }
        }

        // ---- l accumulation in fp32 ALU (overlaps PV tensor drain) ----
        #pragma unroll
        for (int kk = 0; kk < 2; kk++) {
            float a0, a1, b0, b1;
            unpkf16(ph[kk][0], a0, a1); l0 += a0 + a1;
            unpkf16(ph[kk][2], b0, b1); l0 += b0 + b1;
            unpkf16(ph[kk][1], a0, a1); l1 += a0 + a1;
            unpkf16(ph[kk][3], b0, b1); l1 += b0 + b1;
        }

        CP_WAIT2();
        GBAR();

        comp_off += STAGE_BYTES; if (comp_off == NSTAGE * STAGE_BYTES) comp_off = 0;
        fill_off += STAGE_BYTES; if (fill_off == NSTAGE * STAGE_BYTES) fill_off = 0;
    }

    // ---- quad-reduce l (row lives in a lane quad) ----
    l0 += __shfl_xor_sync(0xffffffffu, l0, 1);
    l0 += __shfl_xor_sync(0xffffffffu, l0, 2);
    l1 += __shfl_xor_sync(0xffffffffu, l1, 1);
    l1 += __shfl_xor_sync(0xffffffffu, l1, 2);

    __syncthreads();   // join groups; both done reading stages before smem reuse

    float* sOut = (float*)smbuf;                                // [64][72] fp32
    float* sL   = (float*)(smbuf + NSTAGE * STAGE_BYTES);       // [64] fp32
    const int rloc1 = rloc0 + 8;

    if (wg == 0) {
        #pragma unroll
        for (int nd = 0; nd < 8; nd++) {
            int col = nd * 8 + 2 * tg;
            *(float2*)&sOut[rloc0 * 72 + col] = make_float2(Oa[nd][0], Oa[nd][1]);
            *(float2*)&sOut[rloc1 * 72 + col] = make_float2(Oa[nd][2], Oa[nd][3]);
        }
        if (tg == 0) { sL[rloc0] = l0; sL[rloc1] = l1; }
    }
    __syncthreads();
    if (wg == 1) {
        float inv0 = 1.0f / (l0 + sL[rloc0]);
        float inv1 = 1.0f / (l1 + sL[rloc1]);
        float* o0 = O + ((size_t)((b * Hh + h) * Ll) + r0g) * Ee;
        float* o1 = o0 + (size_t)8 * Ee;
        #pragma unroll
        for (int nd = 0; nd < 8; nd++) {
            int col = nd * 8 + 2 * tg;
            float2 a0 = *(float2*)&sOut[rloc0 * 72 + col];
            float2 a1 = *(float2*)&sOut[rloc1 * 72 + col];
            *(float2*)(o0 + col) = make_float2((Oa[nd][0] + a0.x) * inv0,
                                               (Oa[nd][1] + a0.y) * inv0);
            *(float2*)(o1 + col) = make_float2((Oa[nd][2] + a1.x) * inv1,
                                               (Oa[nd][3] + a1.y) * inv1);
        }
    }
    #undef GBAR
}

extern "C" void kernel_launch(void* const* d_in, const int* in_sizes, int n_in,
                              void* d_out, int out_size)
{
    const float* Q = (const float*)d_in[0];
    const float* K = (const float*)d_in[1];
    const float* V = (const float*)d_in[2];
    const float* M = (const float*)d_in[3];
    float* O = (float*)d_out;

    prep_kernel<<<4096, 256>>>(M, K, V);

    cudaFuncSetAttribute(fa_mma_kernel, cudaFuncAttributeMaxDynamicSharedMemorySize, SM_BYTES);
    dim3 grid(Ll / BM, Hh, Bb);
    fa_mma_kernel<<<grid, 256, SM_BYTES>>>(Q, O);
}